// round 4
// baseline (speedup 1.0000x reference)
#include <cuda_runtime.h>

// Problem dims (fixed by setup_inputs)
#define Bv   1024
#define Tv   80
#define Dv   300
#define Hv   300
#define G4   1200           // 4*H
#define NBLK 304            // persistent grid: 8 p-tiles x 38 j-tiles
#define NTHR 128

// Scratch (device globals — no allocation allowed)
__device__ float g_xpre[(size_t)Tv * G4 * Bv];   // xpre[t][n][p]
__device__ float g_hT[2][Hv * Bv];               // hT[k][p], double buffered
__device__ float g_cT[Hv * Bv];                  // cT[j][p]
__device__ float4 g_whT[Hv * Hv];                // whT[k][j] = 4 gate weights
__device__ int   g_perm[Bv];
__device__ int   g_rank[Bv];
__device__ int   g_act[Tv];
__device__ unsigned g_bar_count;
__device__ unsigned g_bar_sense;

// ---------------------------------------------------------------------------
__global__ void init_kernel(const int* __restrict__ lens) {
    __shared__ int sl[Bv];
    const int tid = threadIdx.x;
    sl[tid] = lens[tid];
    __syncthreads();
    const int L = sl[tid];
    int r = 0;
    for (int b = 0; b < Bv; b++) {
        int L2 = sl[b];
        r += (L2 > L) || (L2 == L && b < tid);
    }
    g_rank[tid] = r;
    g_perm[r]   = tid;
    if (tid < Tv) {
        int c = 0;
        for (int b = 0; b < Bv; b++) c += (sl[b] > tid);
        g_act[tid] = c;
    }
    if (tid == 0) { g_bar_count = 0; g_bar_sense = 0; }
}

__global__ void zero_kernel() {
    int i = blockIdx.x * blockDim.x + threadIdx.x;
    if (i < Hv * Bv) {
        g_hT[0][i] = 0.f;
        g_hT[1][i] = 0.f;
        g_cT[i]    = 0.f;
    }
}

// Transpose Wh[k][g*H+j] -> whT[k*H+j] = float4(g0,g1,g2,g3)
__global__ void trans_kernel(const float* __restrict__ Wh) {
    int i = blockIdx.x * blockDim.x + threadIdx.x;
    if (i < Hv * Hv) {
        int k = i / Hv, j = i - k * Hv;
        const float* r = Wh + k * G4 + j;
        g_whT[i] = make_float4(r[0], r[Hv], r[2 * Hv], r[3 * Hv]);
    }
}

// ---------------------------------------------------------------------------
// Precompute xpre[t][n][p] (fp32 FMA ~peak already)
// ---------------------------------------------------------------------------
__global__ __launch_bounds__(256) void pre_kernel(
    const int*   __restrict__ sent,
    const float* __restrict__ emb,
    const float* __restrict__ Wx,
    const float* __restrict__ bias)
{
    const int t  = blockIdx.z;
    const int p0 = blockIdx.x * 128;
    const int n0 = blockIdx.y * 128;
    if (p0 >= g_act[t]) return;

    __shared__ int   idxs[128];
    __shared__ __align__(16) float es[20][128];
    __shared__ __align__(16) float ws[20][128];

    const int tid = threadIdx.x;
    const int tx  = tid & 15;
    const int ty  = tid >> 4;

    if (tid < 128) idxs[tid] = sent[g_perm[p0 + tid] * Tv + t];
    __syncthreads();

    float acc[8][8];
#pragma unroll
    for (int i = 0; i < 8; i++)
#pragma unroll
        for (int j = 0; j < 8; j++) acc[i][j] = 0.f;

    for (int k0 = 0; k0 < Dv; k0 += 20) {
#pragma unroll
        for (int r = 0; r < 10; r++) {
            int f  = r * 256 + tid;
            int rl = f & 127;
            int kl = f >> 7;
            es[kl][rl] = emb[(size_t)idxs[rl] * Dv + k0 + kl];
            int n = n0 + rl;
            ws[kl][rl] = (n < G4) ? Wx[(k0 + kl) * G4 + n] : 0.f;
        }
        __syncthreads();
#pragma unroll
        for (int k = 0; k < 20; k++) {
            float4 a0 = *(const float4*)&es[k][tx * 4];
            float4 a1 = *(const float4*)&es[k][tx * 4 + 64];
            float4 w0 = *(const float4*)&ws[k][ty * 4];
            float4 w1 = *(const float4*)&ws[k][ty * 4 + 64];
            float a[8] = {a0.x, a0.y, a0.z, a0.w, a1.x, a1.y, a1.z, a1.w};
            float w[8] = {w0.x, w0.y, w0.z, w0.w, w1.x, w1.y, w1.z, w1.w};
#pragma unroll
            for (int ni = 0; ni < 8; ni++)
#pragma unroll
                for (int pi = 0; pi < 8; pi++)
                    acc[ni][pi] = fmaf(w[ni], a[pi], acc[ni][pi]);
        }
        __syncthreads();
    }

#pragma unroll
    for (int ni = 0; ni < 8; ni++) {
        int n = n0 + (ni >> 2) * 64 + ty * 4 + (ni & 3);
        if (n >= G4) continue;
        float bn = bias[n];
        size_t base = ((size_t)t * G4 + n) * Bv + p0;
        float4 v0 = make_float4(acc[ni][0] + bn, acc[ni][1] + bn,
                                acc[ni][2] + bn, acc[ni][3] + bn);
        float4 v1 = make_float4(acc[ni][4] + bn, acc[ni][5] + bn,
                                acc[ni][6] + bn, acc[ni][7] + bn);
        *(float4*)&g_xpre[base + tx * 4]      = v0;
        *(float4*)&g_xpre[base + tx * 4 + 64] = v1;
    }
}

// ---------------------------------------------------------------------------
// Persistent LSTM recurrence
// ---------------------------------------------------------------------------
__device__ __forceinline__ float sigmoidf_(float x) {
    return 1.f / (1.f + __expf(-x));
}
__device__ __forceinline__ float tanhf_(float x) {
    return 1.f - 2.f / (__expf(2.f * x) + 1.f);
}

__device__ __forceinline__ void grid_barrier(unsigned target) {
    __threadfence();
    __syncthreads();
    if (threadIdx.x == 0) {
        if (atomicAdd(&g_bar_count, 1u) == NBLK - 1) {
            g_bar_count = 0;
            __threadfence();
            atomicExch(&g_bar_sense, target);
        } else {
            while (*(volatile unsigned*)&g_bar_sense < target) __nanosleep(64);
        }
    }
    __syncthreads();
}

// Block tile: 128 p x 8 j x 4 gates. Thread: 8 p x 1 j x 4 gates = 32 acc.
// Double-buffered smem, register prefetch, 1 sync per 20-k chunk.
__global__ __launch_bounds__(NTHR, 3) void lstm_kernel()
{
    __shared__ __align__(16) float  hs[2][20][128];
    __shared__ float4 ws[2][20][8];

    const int bid  = blockIdx.x;
    const int tid  = threadIdx.x;
    const int pt   = bid / 38;
    const int jt   = bid - pt * 38;
    const int p0   = pt * 128;
    const int j0   = jt * 8;
    const int pidx = tid & 15;          // 8 consecutive p each
    const int jc   = tid >> 4;          // 0..7
    const int j    = j0 + jc;
    const int pb   = p0 + pidx * 8;
    const bool jok = (j < Hv);

#pragma unroll 1
    for (int t = 0; t < Tv; t++) {
        const int act = g_act[t];
        if (p0 < act) {
            const int par = t & 1;
            const float* __restrict__ hin  = g_hT[par];
            float*       __restrict__ hout = g_hT[par ^ 1];

            float4 ph[5], pw[2];
            auto load_c = [&](int k0) {
#pragma unroll
                for (int i = 0; i < 5; i++) {
                    int f = i * NTHR + tid;
                    int k = f >> 5, x = f & 31;
                    ph[i] = __ldcg((const float4*)&hin[(k0 + k) * Bv + p0 + x * 4]);
                }
#pragma unroll
                for (int i = 0; i < 2; i++) {
                    int f = i * NTHR + tid;
                    if (f < 160) {
                        int k = f >> 3, jj = f & 7;
                        int col = j0 + jj;
                        pw[i] = (col < Hv) ? __ldg(&g_whT[(k0 + k) * Hv + col])
                                           : make_float4(0.f, 0.f, 0.f, 0.f);
                    }
                }
            };
            auto store_c = [&](int buf) {
#pragma unroll
                for (int i = 0; i < 5; i++) {
                    int f = i * NTHR + tid;
                    *(float4*)&hs[buf][f >> 5][(f & 31) * 4] = ph[i];
                }
#pragma unroll
                for (int i = 0; i < 2; i++) {
                    int f = i * NTHR + tid;
                    if (f < 160) ws[buf][f >> 3][f & 7] = pw[i];
                }
            };

            float acc[8][4];
#pragma unroll
            for (int p = 0; p < 8; p++)
#pragma unroll
                for (int g = 0; g < 4; g++) acc[p][g] = 0.f;

            load_c(0);
            store_c(0);
            __syncthreads();

#pragma unroll 1
            for (int c = 0; c < 15; c++) {
                const int cur = c & 1;
                if (c < 14) load_c((c + 1) * 20);
#pragma unroll
                for (int k = 0; k < 20; k++) {
                    float4 a0 = *(const float4*)&hs[cur][k][pidx * 8];
                    float4 a1 = *(const float4*)&hs[cur][k][pidx * 8 + 4];
                    float hv[8] = {a0.x, a0.y, a0.z, a0.w, a1.x, a1.y, a1.z, a1.w};
                    float4 w4 = ws[cur][k][jc];
#pragma unroll
                    for (int p = 0; p < 8; p++) {
                        acc[p][0] = fmaf(hv[p], w4.x, acc[p][0]);
                        acc[p][1] = fmaf(hv[p], w4.y, acc[p][1]);
                        acc[p][2] = fmaf(hv[p], w4.z, acc[p][2]);
                        acc[p][3] = fmaf(hv[p], w4.w, acc[p][3]);
                    }
                }
                if (c < 14) { store_c(cur ^ 1); __syncthreads(); }
            }

            if (jok) {
                const size_t tb = (size_t)t * G4;
                float xp[4][8], hn[8], cn[8];
#pragma unroll
                for (int g = 0; g < 4; g++) {
                    size_t base = (tb + g * Hv + j) * Bv + pb;
                    float4 v0 = __ldcg((const float4*)&g_xpre[base]);
                    float4 v1 = __ldcg((const float4*)&g_xpre[base + 4]);
                    xp[g][0] = v0.x; xp[g][1] = v0.y; xp[g][2] = v0.z; xp[g][3] = v0.w;
                    xp[g][4] = v1.x; xp[g][5] = v1.y; xp[g][6] = v1.z; xp[g][7] = v1.w;
                }
                const int hi = j * Bv + pb;
                float4 c0 = __ldcg((const float4*)&g_cT[hi]);
                float4 c1 = __ldcg((const float4*)&g_cT[hi + 4]);
                float cold[8] = {c0.x, c0.y, c0.z, c0.w, c1.x, c1.y, c1.z, c1.w};
#pragma unroll
                for (int p = 0; p < 8; p++) {
                    float iv = sigmoidf_(acc[p][0] + xp[0][p]);
                    float fv = sigmoidf_(acc[p][1] + xp[1][p]);
                    float gv = tanhf_   (acc[p][2] + xp[2][p]);
                    float ov = sigmoidf_(acc[p][3] + xp[3][p]);
                    cn[p] = fv * cold[p] + iv * gv;
                    hn[p] = ov * tanhf_(cn[p]);
                }
                if (pb + 8 <= act) {   // fully active: vector stores
                    __stcg((float4*)&hout[hi],
                           make_float4(hn[0], hn[1], hn[2], hn[3]));
                    __stcg((float4*)&hout[hi + 4],
                           make_float4(hn[4], hn[5], hn[6], hn[7]));
                    __stcg((float4*)&g_cT[hi],
                           make_float4(cn[0], cn[1], cn[2], cn[3]));
                    __stcg((float4*)&g_cT[hi + 4],
                           make_float4(cn[4], cn[5], cn[6], cn[7]));
                } else {               // straddling thread: masked scalar stores
#pragma unroll
                    for (int p = 0; p < 8; p++) {
                        if (pb + p < act) {
                            __stcg(&hout[hi + p], hn[p]);
                            __stcg(&g_cT[hi + p], cn[p]);
                        }
                    }
                }
            }
        }
        grid_barrier(t + 1);
    }
}

// ---------------------------------------------------------------------------
// Output: out[b, c] = sum_j hT_final[j, rank[b]] * Wout[j, c] + bout[c]
// Final h for batch b lives in buffer lens[b] & 1 (written at t = len-1).
// ---------------------------------------------------------------------------
__global__ void out_kernel(const int* __restrict__ lens,
                           const float* __restrict__ Wout,
                           const float* __restrict__ bout,
                           float* __restrict__ out)
{
    int gwarp = (blockIdx.x * blockDim.x + threadIdx.x) >> 5;
    int lane  = threadIdx.x & 31;
    if (gwarp >= Bv) return;

    const int p = g_rank[gwarp];
    const float* hbuf = g_hT[lens[gwarp] & 1];
    float s0 = 0.f, s1 = 0.f, s2 = 0.f;
    for (int jj = lane; jj < Hv; jj += 32) {
        float hv = hbuf[jj * Bv + p];
        s0 = fmaf(hv, Wout[jj * 3 + 0], s0);
        s1 = fmaf(hv, Wout[jj * 3 + 1], s1);
        s2 = fmaf(hv, Wout[jj * 3 + 2], s2);
    }
#pragma unroll
    for (int off = 16; off > 0; off >>= 1) {
        s0 += __shfl_down_sync(0xffffffffu, s0, off);
        s1 += __shfl_down_sync(0xffffffffu, s1, off);
        s2 += __shfl_down_sync(0xffffffffu, s2, off);
    }
    if (lane == 0) {
        out[gwarp * 3 + 0] = s0 + bout[0];
        out[gwarp * 3 + 1] = s1 + bout[1];
        out[gwarp * 3 + 2] = s2 + bout[2];
    }
}

// ---------------------------------------------------------------------------
extern "C" void kernel_launch(void* const* d_in, const int* in_sizes, int n_in,
                              void* d_out, int out_size)
{
    const int*   sent = (const int*)  d_in[0];
    const int*   lens = (const int*)  d_in[1];
    const float* emb  = (const float*)d_in[2];
    const float* Wx   = (const float*)d_in[3];
    const float* Wh   = (const float*)d_in[4];
    const float* bias = (const float*)d_in[5];
    const float* Wout = (const float*)d_in[6];
    const float* bout = (const float*)d_in[7];
    float* out = (float*)d_out;

    init_kernel<<<1, 1024>>>(lens);
    zero_kernel<<<(Hv * Bv + 255) / 256, 256>>>();
    trans_kernel<<<(Hv * Hv + 255) / 256, 256>>>(Wh);

    dim3 pg(Bv / 128, (G4 + 127) / 128, Tv);   // 8 x 10 x 80
    pre_kernel<<<pg, 256>>>(sent, emb, Wx, bias);

    // one persistent launch for all 80 timesteps
    lstm_kernel<<<NBLK, NTHR>>>();

    out_kernel<<<(Bv * 32 + 127) / 128, 128>>>(lens, Wout, bout, out);
}

// round 5
// speedup vs baseline: 1.0997x; 1.0997x over previous
#include <cuda_runtime.h>

// Problem dims (fixed by setup_inputs)
#define Bv   1024
#define Tv   80
#define Dv   300
#define Hv   300
#define G4   1200           // 4*H
#define NBLK 608            // persistent grid (co-residency guaranteed, 6/SM cap)
#define NTHR 128

// Scratch (device globals — no allocation allowed)
__device__ float g_xpre[(size_t)Tv * G4 * Bv];   // xpre[t][n][p]
__device__ float g_hT[2][Hv * Bv];               // hT[k][p], double buffered
__device__ float g_cT[Hv * Bv];                  // cT[j][p]
__device__ float4 g_whT[Hv * Hv];                // whT[k*H+j] = 4 gate weights
__device__ int   g_perm[Bv];
__device__ int   g_rank[Bv];
__device__ int   g_act[Tv];
__device__ unsigned g_bar_count;
__device__ unsigned g_bar_sense;

// ---------------------------------------------------------------------------
__global__ void init_kernel(const int* __restrict__ lens) {
    __shared__ int sl[Bv];
    const int tid = threadIdx.x;
    sl[tid] = lens[tid];
    __syncthreads();
    const int L = sl[tid];
    int r = 0;
    for (int b = 0; b < Bv; b++) {
        int L2 = sl[b];
        r += (L2 > L) || (L2 == L && b < tid);
    }
    g_rank[tid] = r;
    g_perm[r]   = tid;
    if (tid < Tv) {
        int c = 0;
        for (int b = 0; b < Bv; b++) c += (sl[b] > tid);
        g_act[tid] = c;
    }
    if (tid == 0) { g_bar_count = 0; g_bar_sense = 0; }
}

__global__ void zero_kernel() {
    int i = blockIdx.x * blockDim.x + threadIdx.x;
    if (i < Hv * Bv) {
        g_hT[0][i] = 0.f;
        g_hT[1][i] = 0.f;
        g_cT[i]    = 0.f;
    }
}

// Transpose Wh[k][g*H+j] -> whT[k*H+j] = float4(g0,g1,g2,g3)
__global__ void trans_kernel(const float* __restrict__ Wh) {
    int i = blockIdx.x * blockDim.x + threadIdx.x;
    if (i < Hv * Hv) {
        int k = i / Hv, j = i - k * Hv;
        const float* r = Wh + k * G4 + j;
        g_whT[i] = make_float4(r[0], r[Hv], r[2 * Hv], r[3 * Hv]);
    }
}

// ---------------------------------------------------------------------------
// Precompute xpre[t][n][p]
// ---------------------------------------------------------------------------
__global__ __launch_bounds__(256, 2) void pre_kernel(
    const int*   __restrict__ sent,
    const float* __restrict__ emb,
    const float* __restrict__ Wx,
    const float* __restrict__ bias)
{
    const int t  = blockIdx.z;
    const int p0 = blockIdx.x * 128;
    const int n0 = blockIdx.y * 128;
    if (p0 >= g_act[t]) return;

    __shared__ int   idxs[128];
    __shared__ __align__(16) float es[20][128];
    __shared__ __align__(16) float ws[20][128];

    const int tid = threadIdx.x;
    const int tx  = tid & 15;
    const int ty  = tid >> 4;

    if (tid < 128) idxs[tid] = sent[g_perm[p0 + tid] * Tv + t];
    __syncthreads();

    float acc[8][8];
#pragma unroll
    for (int i = 0; i < 8; i++)
#pragma unroll
        for (int j = 0; j < 8; j++) acc[i][j] = 0.f;

    for (int k0 = 0; k0 < Dv; k0 += 20) {
#pragma unroll
        for (int r = 0; r < 10; r++) {
            int f  = r * 256 + tid;
            int rl = f & 127;
            int kl = f >> 7;
            es[kl][rl] = emb[(size_t)idxs[rl] * Dv + k0 + kl];
            int n = n0 + rl;
            ws[kl][rl] = (n < G4) ? Wx[(k0 + kl) * G4 + n] : 0.f;
        }
        __syncthreads();
#pragma unroll
        for (int k = 0; k < 20; k++) {
            float4 a0 = *(const float4*)&es[k][tx * 4];
            float4 a1 = *(const float4*)&es[k][tx * 4 + 64];
            float4 w0 = *(const float4*)&ws[k][ty * 4];
            float4 w1 = *(const float4*)&ws[k][ty * 4 + 64];
            float a[8] = {a0.x, a0.y, a0.z, a0.w, a1.x, a1.y, a1.z, a1.w};
            float w[8] = {w0.x, w0.y, w0.z, w0.w, w1.x, w1.y, w1.z, w1.w};
#pragma unroll
            for (int ni = 0; ni < 8; ni++)
#pragma unroll
                for (int pi = 0; pi < 8; pi++)
                    acc[ni][pi] = fmaf(w[ni], a[pi], acc[ni][pi]);
        }
        __syncthreads();
    }

#pragma unroll
    for (int ni = 0; ni < 8; ni++) {
        int n = n0 + (ni >> 2) * 64 + ty * 4 + (ni & 3);
        if (n >= G4) continue;
        float bn = bias[n];
        size_t base = ((size_t)t * G4 + n) * Bv + p0;
        float4 v0 = make_float4(acc[ni][0] + bn, acc[ni][1] + bn,
                                acc[ni][2] + bn, acc[ni][3] + bn);
        float4 v1 = make_float4(acc[ni][4] + bn, acc[ni][5] + bn,
                                acc[ni][6] + bn, acc[ni][7] + bn);
        *(float4*)&g_xpre[base + tx * 4]      = v0;
        *(float4*)&g_xpre[base + tx * 4 + 64] = v1;
    }
}

// ---------------------------------------------------------------------------
// Persistent LSTM recurrence: one launch, 80 steps, software grid barrier.
// ---------------------------------------------------------------------------
__device__ __forceinline__ float sigmoidf_(float x) {
    return 1.f / (1.f + __expf(-x));
}
__device__ __forceinline__ float tanhf_(float x) {
    return 1.f - 2.f / (__expf(2.f * x) + 1.f);
}

__device__ __forceinline__ void grid_barrier(unsigned target) {
    __threadfence();
    __syncthreads();
    if (threadIdx.x == 0) {
        if (atomicAdd(&g_bar_count, 1u) == NBLK - 1) {
            g_bar_count = 0;
            __threadfence();
            atomicExch(&g_bar_sense, target);
        } else {
            while (*(volatile unsigned*)&g_bar_sense < target) __nanosleep(64);
        }
    }
    __syncthreads();
}

// One tile of the step GEMM: 64 p x W j-cols x 4 gates, 128 threads.
// Double-buffered smem, register prefetch, single sync per k-chunk (KT=20).
// No h-forwarding: masked lanes simply skip stores (act is non-increasing).
template<int W>
__device__ __forceinline__ void step_tile(
    float hs[2][20][64], float4 ws[2][20][8],
    const float* __restrict__ hin, float* __restrict__ hout,
    int t, int p0, int j0, int act)
{
    constexpr int TPJ = NTHR / W;        // threads per j column (16/32/64)
    constexpr int PPT = 64 / TPJ;        // p per thread (4/2/1)
    constexpr int JSH = (W == 8) ? 3 : (W == 4 ? 2 : 1);
    constexpr int NW4 = 20 * W;          // ws float4 count per chunk
    constexpr int WLN = (NW4 + NTHR - 1) / NTHR;
    const int tid  = threadIdx.x;
    const int pidx = tid % TPJ;
    const int jc   = tid / TPJ;
    const int j    = j0 + jc;

    float4 ph[3];
    float4 pw[WLN];

    auto load_c = [&](int k0) {
#pragma unroll
        for (int i = 0; i < 3; i++) {
            int f = i * NTHR + tid;              // 320 float4 total (20k x 16)
            if (f < 320)
                ph[i] = __ldcg((const float4*)&hin[(k0 + (f >> 4)) * Bv + p0
                                                   + (f & 15) * 4]);
        }
#pragma unroll
        for (int i = 0; i < WLN; i++) {
            int idx = i * NTHR + tid;
            if (idx < NW4) {
                int k   = idx >> JSH;
                int jj  = idx & (W - 1);
                int col = j0 + jj;
                pw[i] = (col < Hv) ? __ldg(&g_whT[(k0 + k) * Hv + col])
                                   : make_float4(0.f, 0.f, 0.f, 0.f);
            }
        }
    };
    auto store_c = [&](int buf) {
#pragma unroll
        for (int i = 0; i < 3; i++) {
            int f = i * NTHR + tid;
            if (f < 320)
                *(float4*)&hs[buf][f >> 4][(f & 15) * 4] = ph[i];
        }
#pragma unroll
        for (int i = 0; i < WLN; i++) {
            int idx = i * NTHR + tid;
            if (idx < NW4) ws[buf][idx >> JSH][idx & (W - 1)] = pw[i];
        }
    };

    float acc[PPT][4];
#pragma unroll
    for (int p = 0; p < PPT; p++)
#pragma unroll
        for (int g = 0; g < 4; g++) acc[p][g] = 0.f;

    load_c(0);
    store_c(0);
    __syncthreads();

#pragma unroll 1
    for (int c = 0; c < 15; c++) {
        const int cur = c & 1;
        if (c < 14) load_c((c + 1) * 20);
#pragma unroll
        for (int k = 0; k < 20; k++) {
            float hv[PPT];
            if (PPT == 4) {
                float4 h4 = *(const float4*)&hs[cur][k][pidx * 4];
                hv[0] = h4.x; hv[1] = h4.y; hv[2] = h4.z; hv[3] = h4.w;
            } else if (PPT == 2) {
                float2 h2 = *(const float2*)&hs[cur][k][pidx * 2];
                hv[0] = h2.x; hv[1] = h2.y;
            } else {
                hv[0] = hs[cur][k][pidx];
            }
            float4 w4 = ws[cur][k][jc];
#pragma unroll
            for (int p = 0; p < PPT; p++) {
                acc[p][0] = fmaf(hv[p], w4.x, acc[p][0]);
                acc[p][1] = fmaf(hv[p], w4.y, acc[p][1]);
                acc[p][2] = fmaf(hv[p], w4.z, acc[p][2]);
                acc[p][3] = fmaf(hv[p], w4.w, acc[p][3]);
            }
        }
        if (c < 14) { store_c(cur ^ 1); __syncthreads(); }
    }

    if (j >= Hv) return;

    const size_t tb = (size_t)t * G4;
    const int pb = p0 + pidx * PPT;
    const int hi = j * Bv + pb;

    if (PPT == 4 && pb + 4 <= act) {       // fast path: fully active, vector
        float xp[4][4];
#pragma unroll
        for (int g = 0; g < 4; g++) {
            float4 v = __ldcg((const float4*)&g_xpre[(tb + g * Hv + j) * Bv + pb]);
            xp[g][0] = v.x; xp[g][1] = v.y; xp[g][2] = v.z; xp[g][3] = v.w;
        }
        float4 c4 = __ldcg((const float4*)&g_cT[hi]);
        float cold[4] = {c4.x, c4.y, c4.z, c4.w};
        float hn[4], cn[4];
#pragma unroll
        for (int p = 0; p < 4; p++) {
            float iv = sigmoidf_(acc[p][0] + xp[0][p]);
            float fv = sigmoidf_(acc[p][1] + xp[1][p]);
            float gv = tanhf_   (acc[p][2] + xp[2][p]);
            float ov = sigmoidf_(acc[p][3] + xp[3][p]);
            cn[p] = fv * cold[p] + iv * gv;
            hn[p] = ov * tanhf_(cn[p]);
        }
        __stcg((float4*)&hout[hi], make_float4(hn[0], hn[1], hn[2], hn[3]));
        __stcg((float4*)&g_cT[hi], make_float4(cn[0], cn[1], cn[2], cn[3]));
    } else {                                // straddle / narrow: scalar masked
#pragma unroll
        for (int p = 0; p < PPT; p++) {
            const int pp = pb + p;
            if (pp >= act) continue;
            float gi = acc[p][0] + __ldcg(&g_xpre[(tb + 0 * Hv + j) * Bv + pp]);
            float gf = acc[p][1] + __ldcg(&g_xpre[(tb + 1 * Hv + j) * Bv + pp]);
            float gg = acc[p][2] + __ldcg(&g_xpre[(tb + 2 * Hv + j) * Bv + pp]);
            float go = acc[p][3] + __ldcg(&g_xpre[(tb + 3 * Hv + j) * Bv + pp]);
            float iv = sigmoidf_(gi);
            float fv = sigmoidf_(gf);
            float gv = tanhf_(gg);
            float ov = sigmoidf_(go);
            float cold = __ldcg(&g_cT[hi + p]);
            float cnew = fv * cold + iv * gv;
            float hnew = ov * tanhf_(cnew);
            __stcg(&g_cT[hi + p], cnew);
            __stcg(&hout[hi + p], hnew);
        }
    }
}

__global__ __launch_bounds__(NTHR, 6) void lstm_kernel()
{
    __shared__ __align__(16) float  hs[2][20][64];
    __shared__ float4 ws[2][20][8];
    const int bid = blockIdx.x;

#pragma unroll 1
    for (int t = 0; t < Tv; t++) {
        const int par = t & 1;
        const float* hin  = g_hT[par];
        float*       hout = g_hT[par ^ 1];
        const int act = g_act[t];
        const int na  = (act + 63) >> 6;

        // dynamic re-tiling: j-width shrinks as active prefix shrinks
        int w, njt;
        if      (na >= 9) { w = 8; njt = 38;  }
        else if (na >= 5) { w = 4; njt = 75;  }
        else              { w = 2; njt = 150; }

        if (bid < na * njt) {
            int pt = bid / njt;
            int jt = bid - pt * njt;
            if (w == 8)
                step_tile<8>(hs, ws, hin, hout, t, pt * 64, jt * 8, act);
            else if (w == 4)
                step_tile<4>(hs, ws, hin, hout, t, pt * 64, jt * 4, act);
            else
                step_tile<2>(hs, ws, hin, hout, t, pt * 64, jt * 2, act);
        }
        grid_barrier(t + 1);
    }
}

// ---------------------------------------------------------------------------
// Output: final h for batch b lives in buffer lens[b] & 1 (written at len-1).
// ---------------------------------------------------------------------------
__global__ void out_kernel(const int* __restrict__ lens,
                           const float* __restrict__ Wout,
                           const float* __restrict__ bout,
                           float* __restrict__ out)
{
    int gwarp = (blockIdx.x * blockDim.x + threadIdx.x) >> 5;
    int lane  = threadIdx.x & 31;
    if (gwarp >= Bv) return;

    const int p = g_rank[gwarp];
    const float* hbuf = g_hT[lens[gwarp] & 1];
    float s0 = 0.f, s1 = 0.f, s2 = 0.f;
    for (int jj = lane; jj < Hv; jj += 32) {
        float hv = hbuf[jj * Bv + p];
        s0 = fmaf(hv, Wout[jj * 3 + 0], s0);
        s1 = fmaf(hv, Wout[jj * 3 + 1], s1);
        s2 = fmaf(hv, Wout[jj * 3 + 2], s2);
    }
#pragma unroll
    for (int off = 16; off > 0; off >>= 1) {
        s0 += __shfl_down_sync(0xffffffffu, s0, off);
        s1 += __shfl_down_sync(0xffffffffu, s1, off);
        s2 += __shfl_down_sync(0xffffffffu, s2, off);
    }
    if (lane == 0) {
        out[gwarp * 3 + 0] = s0 + bout[0];
        out[gwarp * 3 + 1] = s1 + bout[1];
        out[gwarp * 3 + 2] = s2 + bout[2];
    }
}

// ---------------------------------------------------------------------------
extern "C" void kernel_launch(void* const* d_in, const int* in_sizes, int n_in,
                              void* d_out, int out_size)
{
    const int*   sent = (const int*)  d_in[0];
    const int*   lens = (const int*)  d_in[1];
    const float* emb  = (const float*)d_in[2];
    const float* Wx   = (const float*)d_in[3];
    const float* Wh   = (const float*)d_in[4];
    const float* bias = (const float*)d_in[5];
    const float* Wout = (const float*)d_in[6];
    const float* bout = (const float*)d_in[7];
    float* out = (float*)d_out;

    init_kernel<<<1, 1024>>>(lens);
    zero_kernel<<<(Hv * Bv + 255) / 256, 256>>>();
    trans_kernel<<<(Hv * Hv + 255) / 256, 256>>>(Wh);

    dim3 pg(Bv / 128, (G4 + 127) / 128, Tv);   // 8 x 10 x 80
    pre_kernel<<<pg, 256>>>(sent, emb, Wx, bias);

    // one persistent launch for all 80 timesteps
    lstm_kernel<<<NBLK, NTHR>>>();

    out_kernel<<<(Bv * 32 + 127) / 128, 128>>>(lens, Wout, bout, out);
}

// round 6
// speedup vs baseline: 1.2885x; 1.1717x over previous
#include <cuda_runtime.h>

// Problem dims (fixed by setup_inputs)
#define Bv   1024
#define Tv   80
#define Dv   300
#define Hv   300
#define G4   1200           // 4*H
#define NBLK 570            // 15 p-groups x 38 j-tiles; 4/SM co-resident (46KB smem)
#define NTHR 128

// Scratch (device globals — no allocation allowed)
__device__ float g_xpre[(size_t)Tv * G4 * Bv];   // xpre[t][n][p]
__device__ float g_hT[2][Hv * Bv];               // hT[k][p], double buffered
__device__ float g_cT[Hv * Bv];                  // cT[j][p]
__device__ float4 g_whT[Hv * Hv];                // whT[k*H+j] = 4 gate weights
__device__ int   g_perm[Bv];
__device__ int   g_rank[Bv];
__device__ int   g_act[Tv];
__device__ unsigned g_bar_count;
__device__ unsigned g_bar_sense;

// ---------------------------------------------------------------------------
__global__ void init_kernel(const int* __restrict__ lens) {
    __shared__ int sl[Bv];
    const int tid = threadIdx.x;
    sl[tid] = lens[tid];
    __syncthreads();
    const int L = sl[tid];
    int r = 0;
    for (int b = 0; b < Bv; b++) {
        int L2 = sl[b];
        r += (L2 > L) || (L2 == L && b < tid);
    }
    g_rank[tid] = r;
    g_perm[r]   = tid;
    if (tid < Tv) {
        int c = 0;
        for (int b = 0; b < Bv; b++) c += (sl[b] > tid);
        g_act[tid] = c;
    }
    if (tid == 0) { g_bar_count = 0; g_bar_sense = 0; }
}

__global__ void zero_kernel() {
    int i = blockIdx.x * blockDim.x + threadIdx.x;
    if (i < Hv * Bv) {
        g_hT[0][i] = 0.f;
        g_hT[1][i] = 0.f;
        g_cT[i]    = 0.f;
    }
}

// Transpose Wh[k][g*H+j] -> whT[k*H+j] = float4(g0,g1,g2,g3)
__global__ void trans_kernel(const float* __restrict__ Wh) {
    int i = blockIdx.x * blockDim.x + threadIdx.x;
    if (i < Hv * Hv) {
        int k = i / Hv, j = i - k * Hv;
        const float* r = Wh + k * G4 + j;
        g_whT[i] = make_float4(r[0], r[Hv], r[2 * Hv], r[3 * Hv]);
    }
}

// ---------------------------------------------------------------------------
// Precompute xpre[t][n][p]
// ---------------------------------------------------------------------------
__global__ __launch_bounds__(256, 2) void pre_kernel(
    const int*   __restrict__ sent,
    const float* __restrict__ emb,
    const float* __restrict__ Wx,
    const float* __restrict__ bias)
{
    const int t  = blockIdx.z;
    const int p0 = blockIdx.x * 128;
    const int n0 = blockIdx.y * 128;
    if (p0 >= g_act[t]) return;

    __shared__ int   idxs[128];
    __shared__ __align__(16) float es[20][128];
    __shared__ __align__(16) float ws[20][128];

    const int tid = threadIdx.x;
    const int tx  = tid & 15;
    const int ty  = tid >> 4;

    if (tid < 128) idxs[tid] = sent[g_perm[p0 + tid] * Tv + t];
    __syncthreads();

    float acc[8][8];
#pragma unroll
    for (int i = 0; i < 8; i++)
#pragma unroll
        for (int j = 0; j < 8; j++) acc[i][j] = 0.f;

    for (int k0 = 0; k0 < Dv; k0 += 20) {
#pragma unroll
        for (int r = 0; r < 10; r++) {
            int f  = r * 256 + tid;
            int rl = f & 127;
            int kl = f >> 7;
            es[kl][rl] = emb[(size_t)idxs[rl] * Dv + k0 + kl];
            int n = n0 + rl;
            ws[kl][rl] = (n < G4) ? Wx[(k0 + kl) * G4 + n] : 0.f;
        }
        __syncthreads();
#pragma unroll
        for (int k = 0; k < 20; k++) {
            float4 a0 = *(const float4*)&es[k][tx * 4];
            float4 a1 = *(const float4*)&es[k][tx * 4 + 64];
            float4 w0 = *(const float4*)&ws[k][ty * 4];
            float4 w1 = *(const float4*)&ws[k][ty * 4 + 64];
            float a[8] = {a0.x, a0.y, a0.z, a0.w, a1.x, a1.y, a1.z, a1.w};
            float w[8] = {w0.x, w0.y, w0.z, w0.w, w1.x, w1.y, w1.z, w1.w};
#pragma unroll
            for (int ni = 0; ni < 8; ni++)
#pragma unroll
                for (int pi = 0; pi < 8; pi++)
                    acc[ni][pi] = fmaf(w[ni], a[pi], acc[ni][pi]);
        }
        __syncthreads();
    }

#pragma unroll
    for (int ni = 0; ni < 8; ni++) {
        int n = n0 + (ni >> 2) * 64 + ty * 4 + (ni & 3);
        if (n >= G4) continue;
        float bn = bias[n];
        size_t base = ((size_t)t * G4 + n) * Bv + p0;
        float4 v0 = make_float4(acc[ni][0] + bn, acc[ni][1] + bn,
                                acc[ni][2] + bn, acc[ni][3] + bn);
        float4 v1 = make_float4(acc[ni][4] + bn, acc[ni][5] + bn,
                                acc[ni][6] + bn, acc[ni][7] + bn);
        *(float4*)&g_xpre[base + tx * 4]      = v0;
        *(float4*)&g_xpre[base + tx * 4 + 64] = v1;
    }
}

// ---------------------------------------------------------------------------
// Persistent LSTM recurrence with Wh RESIDENT in shared memory per phase.
// ---------------------------------------------------------------------------
__device__ __forceinline__ float sigmoidf_(float x) {
    return 1.f / (1.f + __expf(-x));
}
__device__ __forceinline__ float tanhf_(float x) {
    return 1.f - 2.f / (__expf(2.f * x) + 1.f);
}

__device__ __forceinline__ void grid_barrier(unsigned target) {
    __threadfence();
    __syncthreads();
    if (threadIdx.x == 0) {
        if (atomicAdd(&g_bar_count, 1u) == NBLK - 1) {
            g_bar_count = 0;
            __threadfence();
            atomicExch(&g_bar_sense, target);
        } else {
            while (*(volatile unsigned*)&g_bar_sense < target) __nanosleep(64);
        }
    }
    __syncthreads();
}

// One tile: 64 p x W j-cols x 4 gates, 128 threads. Wh already in ws4 (smem,
// resident for the whole phase). Only h is staged per 15-k chunk (dbl-buffer).
template<int W>
__device__ __forceinline__ void step_tile(
    float hs[2][15][64], const float4* __restrict__ ws4,
    const float* __restrict__ hin, float* __restrict__ hout,
    int t, int p0, int act)
{
    constexpr int TPJ = NTHR / W;        // 16 / 32 / 64
    constexpr int PPT = 64 / TPJ;        // 4 / 2 / 1
    const int tid  = threadIdx.x;
    const int pidx = tid % TPJ;
    const int jc   = tid / TPJ;          // ws4 holds W j-cols; j = j0 + jc

    float4 ph[2];
    auto load_c = [&](int k0) {
#pragma unroll
        for (int i = 0; i < 2; i++) {
            int f = i * NTHR + tid;      // 240 float4 total (15k x 16)
            if (f < 240)
                ph[i] = __ldcg((const float4*)&hin[(k0 + (f >> 4)) * Bv + p0
                                                   + ((f & 15) << 2)]);
        }
    };
    auto store_c = [&](int buf) {
#pragma unroll
        for (int i = 0; i < 2; i++) {
            int f = i * NTHR + tid;
            if (f < 240)
                *(float4*)&hs[buf][f >> 4][(f & 15) << 2] = ph[i];
        }
    };

    float acc[PPT][4];
#pragma unroll
    for (int p = 0; p < PPT; p++)
#pragma unroll
        for (int g = 0; g < 4; g++) acc[p][g] = 0.f;

    load_c(0);
    store_c(0);
    __syncthreads();

#pragma unroll 1
    for (int c = 0; c < 20; c++) {
        const int cur = c & 1;
        if (c < 19) load_c((c + 1) * 15);
#pragma unroll
        for (int kk = 0; kk < 15; kk++) {
            const int k = c * 15 + kk;
            float hv[PPT];
            if (PPT == 4) {
                float4 h4 = *(const float4*)&hs[cur][kk][pidx * 4];
                hv[0] = h4.x; hv[1] = h4.y; hv[2] = h4.z; hv[3] = h4.w;
            } else if (PPT == 2) {
                float2 h2 = *(const float2*)&hs[cur][kk][pidx * 2];
                hv[0] = h2.x; hv[1] = h2.y;
            } else {
                hv[0] = hs[cur][kk][pidx];
            }
            float4 w4 = ws4[k * W + jc];
#pragma unroll
            for (int p = 0; p < PPT; p++) {
                acc[p][0] = fmaf(hv[p], w4.x, acc[p][0]);
                acc[p][1] = fmaf(hv[p], w4.y, acc[p][1]);
                acc[p][2] = fmaf(hv[p], w4.z, acc[p][2]);
                acc[p][3] = fmaf(hv[p], w4.w, acc[p][3]);
            }
        }
        if (c < 19) { store_c(cur ^ 1); __syncthreads(); }
    }

    // epilogue (j passed implicitly via ws4 slice; recompute actual j outside)
    // caller guarantees ws4 cols beyond Hv are zero; mask j here:
    extern __shared__ int _dummy[];      // (unused; silences nothing) 
    (void)_dummy;
    // j is provided through ws4 slice; we need real j index for memory:
    // -> handled by caller passing j0 via p0-independent lambda is complex;
    //    instead we recompute using the global below.
    return;
}

// Full tile incl. epilogue: wraps compute + activation/state update.
template<int W>
__device__ __forceinline__ void step_tile_full(
    float hs[2][15][64], const float4* __restrict__ ws4,
    const float* __restrict__ hin, float* __restrict__ hout,
    int t, int p0, int j0, int act)
{
    constexpr int TPJ = NTHR / W;
    constexpr int PPT = 64 / TPJ;
    const int tid  = threadIdx.x;
    const int pidx = tid % TPJ;
    const int jc   = tid / TPJ;
    const int j    = j0 + jc;

    float4 ph[2];
    auto load_c = [&](int k0) {
#pragma unroll
        for (int i = 0; i < 2; i++) {
            int f = i * NTHR + tid;
            if (f < 240)
                ph[i] = __ldcg((const float4*)&hin[(k0 + (f >> 4)) * Bv + p0
                                                   + ((f & 15) << 2)]);
        }
    };
    auto store_c = [&](int buf) {
#pragma unroll
        for (int i = 0; i < 2; i++) {
            int f = i * NTHR + tid;
            if (f < 240)
                *(float4*)&hs[buf][f >> 4][(f & 15) << 2] = ph[i];
        }
    };

    float acc[PPT][4];
#pragma unroll
    for (int p = 0; p < PPT; p++)
#pragma unroll
        for (int g = 0; g < 4; g++) acc[p][g] = 0.f;

    load_c(0);
    store_c(0);
    __syncthreads();

#pragma unroll 1
    for (int c = 0; c < 20; c++) {
        const int cur = c & 1;
        if (c < 19) load_c((c + 1) * 15);
#pragma unroll
        for (int kk = 0; kk < 15; kk++) {
            const int k = c * 15 + kk;
            float hv[PPT];
            if (PPT == 4) {
                float4 h4 = *(const float4*)&hs[cur][kk][pidx * 4];
                hv[0] = h4.x; hv[1] = h4.y; hv[2] = h4.z; hv[3] = h4.w;
            } else if (PPT == 2) {
                float2 h2 = *(const float2*)&hs[cur][kk][pidx * 2];
                hv[0] = h2.x; hv[1] = h2.y;
            } else {
                hv[0] = hs[cur][kk][pidx];
            }
            float4 w4 = ws4[k * W + jc];
#pragma unroll
            for (int p = 0; p < PPT; p++) {
                acc[p][0] = fmaf(hv[p], w4.x, acc[p][0]);
                acc[p][1] = fmaf(hv[p], w4.y, acc[p][1]);
                acc[p][2] = fmaf(hv[p], w4.z, acc[p][2]);
                acc[p][3] = fmaf(hv[p], w4.w, acc[p][3]);
            }
        }
        if (c < 19) { store_c(cur ^ 1); __syncthreads(); }
    }

    if (j >= Hv) return;

    const size_t tb = (size_t)t * G4;
    const int pb = p0 + pidx * PPT;
    const int hi = j * Bv + pb;

    if (PPT == 4 && pb + 4 <= act) {       // fully active: vector path
        float xp[4][4];
#pragma unroll
        for (int g = 0; g < 4; g++) {
            float4 v = __ldcg((const float4*)&g_xpre[(tb + g * Hv + j) * Bv + pb]);
            xp[g][0] = v.x; xp[g][1] = v.y; xp[g][2] = v.z; xp[g][3] = v.w;
        }
        float4 c4 = __ldcg((const float4*)&g_cT[hi]);
        float cold[4] = {c4.x, c4.y, c4.z, c4.w};
        float hn[4], cn[4];
#pragma unroll
        for (int p = 0; p < 4; p++) {
            float iv = sigmoidf_(acc[p][0] + xp[0][p]);
            float fv = sigmoidf_(acc[p][1] + xp[1][p]);
            float gv = tanhf_   (acc[p][2] + xp[2][p]);
            float ov = sigmoidf_(acc[p][3] + xp[3][p]);
            cn[p] = fv * cold[p] + iv * gv;
            hn[p] = ov * tanhf_(cn[p]);
        }
        __stcg((float4*)&hout[hi], make_float4(hn[0], hn[1], hn[2], hn[3]));
        __stcg((float4*)&g_cT[hi], make_float4(cn[0], cn[1], cn[2], cn[3]));
    } else {                                // straddle / narrow: masked scalar
#pragma unroll
        for (int p = 0; p < PPT; p++) {
            const int pp = pb + p;
            if (pp >= act) continue;
            float gi = acc[p][0] + __ldcg(&g_xpre[(tb + 0 * Hv + j) * Bv + pp]);
            float gf = acc[p][1] + __ldcg(&g_xpre[(tb + 1 * Hv + j) * Bv + pp]);
            float gg = acc[p][2] + __ldcg(&g_xpre[(tb + 2 * Hv + j) * Bv + pp]);
            float go = acc[p][3] + __ldcg(&g_xpre[(tb + 3 * Hv + j) * Bv + pp]);
            float iv = sigmoidf_(gi);
            float fv = sigmoidf_(gf);
            float gv = tanhf_(gg);
            float ov = sigmoidf_(go);
            float cold = __ldcg(&g_cT[hi + p]);
            float cnew = fv * cold + iv * gv;
            float hnew = ov * tanhf_(cnew);
            __stcg(&g_cT[hi + p], cnew);
            __stcg(&hout[hi + p], hnew);
        }
    }
}

__global__ __launch_bounds__(NTHR, 4) void lstm_kernel()
{
    __shared__ __align__(16) float  hs[2][15][64];   // 7.5 KB, dbl-buffered
    __shared__ float4 ws4[2400];                     // 37.5 KB, phase-resident Wh

    const int bid = blockIdx.x;
    const int tid = threadIdx.x;
    int wlast = 0;

#pragma unroll 1
    for (int t = 0; t < Tv; t++) {
        const int act = g_act[t];
        const int na  = (act + 63) >> 6;
        const float* hin  = g_hT[t & 1];
        float*       hout = g_hT[(t & 1) ^ 1];

        int w, njt, lw;
        if      (na >= 9) { w = 8; njt = 38;  lw = 3; }
        else if (na >= 5) { w = 4; njt = 75;  lw = 2; }
        else              { w = 2; njt = 150; lw = 1; }
        const int jt  = bid % njt;
        const int ptb = bid / njt;
        const int j0  = jt * w;

        if (w != wlast) {    // phase change: (re)load this block's Wh slice
            for (int idx = tid; idx < 300 * w; idx += NTHR) {
                int k   = idx >> lw;
                int jj  = idx & (w - 1);
                int col = j0 + jj;
                ws4[idx] = (col < Hv) ? g_whT[k * Hv + col]
                                      : make_float4(0.f, 0.f, 0.f, 0.f);
            }
            wlast = w;
            __syncthreads();
        }

        int stride;
        if      (w == 8) stride = 15;                    // 570 = 15*38 exact
        else if (w == 4) stride = (jt < 45)  ? 8 : 7;    // 570 = 7*75+45
        else             stride = (jt < 120) ? 4 : 3;    // 570 = 3*150+120

        if (w == 8) {
            for (int pp = ptb; pp * 64 < act; pp += stride)
                step_tile_full<8>(hs, ws4, hin, hout, t, pp * 64, j0, act);
        } else if (w == 4) {
            for (int pp = ptb; pp * 64 < act; pp += stride)
                step_tile_full<4>(hs, ws4, hin, hout, t, pp * 64, j0, act);
        } else {
            for (int pp = ptb; pp * 64 < act; pp += stride)
                step_tile_full<2>(hs, ws4, hin, hout, t, pp * 64, j0, act);
        }
        grid_barrier(t + 1);
    }
}

// ---------------------------------------------------------------------------
// Output: final h for batch b lives in buffer lens[b] & 1 (written at len-1).
// ---------------------------------------------------------------------------
__global__ void out_kernel(const int* __restrict__ lens,
                           const float* __restrict__ Wout,
                           const float* __restrict__ bout,
                           float* __restrict__ out)
{
    int gwarp = (blockIdx.x * blockDim.x + threadIdx.x) >> 5;
    int lane  = threadIdx.x & 31;
    if (gwarp >= Bv) return;

    const int p = g_rank[gwarp];
    const float* hbuf = g_hT[lens[gwarp] & 1];
    float s0 = 0.f, s1 = 0.f, s2 = 0.f;
    for (int jj = lane; jj < Hv; jj += 32) {
        float hv = hbuf[jj * Bv + p];
        s0 = fmaf(hv, Wout[jj * 3 + 0], s0);
        s1 = fmaf(hv, Wout[jj * 3 + 1], s1);
        s2 = fmaf(hv, Wout[jj * 3 + 2], s2);
    }
#pragma unroll
    for (int off = 16; off > 0; off >>= 1) {
        s0 += __shfl_down_sync(0xffffffffu, s0, off);
        s1 += __shfl_down_sync(0xffffffffu, s1, off);
        s2 += __shfl_down_sync(0xffffffffu, s2, off);
    }
    if (lane == 0) {
        out[gwarp * 3 + 0] = s0 + bout[0];
        out[gwarp * 3 + 1] = s1 + bout[1];
        out[gwarp * 3 + 2] = s2 + bout[2];
    }
}

// ---------------------------------------------------------------------------
extern "C" void kernel_launch(void* const* d_in, const int* in_sizes, int n_in,
                              void* d_out, int out_size)
{
    const int*   sent = (const int*)  d_in[0];
    const int*   lens = (const int*)  d_in[1];
    const float* emb  = (const float*)d_in[2];
    const float* Wx   = (const float*)d_in[3];
    const float* Wh   = (const float*)d_in[4];
    const float* bias = (const float*)d_in[5];
    const float* Wout = (const float*)d_in[6];
    const float* bout = (const float*)d_in[7];
    float* out = (float*)d_out;

    init_kernel<<<1, 1024>>>(lens);
    zero_kernel<<<(Hv * Bv + 255) / 256, 256>>>();
    trans_kernel<<<(Hv * Hv + 255) / 256, 256>>>(Wh);

    dim3 pg(Bv / 128, (G4 + 127) / 128, Tv);   // 8 x 10 x 80
    pre_kernel<<<pg, 256>>>(sent, emb, Wx, bias);

    // one persistent launch for all 80 timesteps (Wh phase-resident in smem)
    lstm_kernel<<<NBLK, NTHR>>>();

    out_kernel<<<(Bv * 32 + 127) / 128, 128>>>(lens, Wout, bout, out);
}